// round 4
// baseline (speedup 1.0000x reference)
#include <cuda_runtime.h>
#include <math.h>

#define Bz 64
#define Tz 512
#define Hz 1024
#define H2z 2048
#define NCTA 128
#define NS1 32             // GEMM1 k-slices (K=32 each)
#define NS2 16             // GEMM2 k-slices (K=64 each)
#define KCH 32             // staging chunk

// Scratch (__device__ globals; no allocation allowed)
__device__ float g_xw[(size_t)32768 * 1024];   // [B*T, H]
__device__ float g_h[Bz * Hz];
__device__ float g_hrnn[Bz * Hz];
__device__ float g_p1[NS1 * Bz * Hz];          // 8 MB
__device__ float g_p2[NS2 * Bz * H2z];         // 8 MB
__device__ float g_lpp[Bz][2];
__device__ unsigned g_flags[NCTA];
__device__ unsigned g_epoch;

typedef unsigned long long ull;
__device__ __forceinline__ ull dup2(float a) {
    ull r; asm("mov.b64 %0,{%1,%1};" : "=l"(r) : "f"(a)); return r;
}
__device__ __forceinline__ void fma2(ull& acc, ull a, ull w) {
    asm("fma.rn.f32x2 %0,%1,%2,%0;" : "+l"(acc) : "l"(a), "l"(w));
}

struct Smem {
    float As[64][36];      // A chunk, row-major [row][k] (broadcast reads)
    float Ws[KCH][258];    // W chunk, transposed [k][n] (LDS.64 stride-2 reads)
};

// Flag-array grid barrier with persistent epoch (replay-safe, no resets).
__device__ __forceinline__ void grid_sync(unsigned& gen) {
    __syncthreads();
    gen++;
    const int tid = threadIdx.x;
    if (tid == 0)
        asm volatile("st.release.gpu.u32 [%0], %1;"
                     :: "l"(&g_flags[blockIdx.x]), "r"(gen) : "memory");
    if (tid < NCTA) {
        unsigned v;
        do {
            asm volatile("ld.acquire.gpu.u32 %0, [%1];"
                         : "=r"(v) : "l"(&g_flags[tid]) : "memory");
        } while ((int)(v - gen) < 0);
    }
    __syncthreads();
}

// 64x256 output tile. A row-major [64][1024]; W row-major (pass W + n0*1024).
// 512 threads: tx=tid&31, ty=tid>>5. rows 4ty..4ty+3, cols m*64+2tx (m=0..3).
template<bool CG>
__device__ __forceinline__ void gemm_tile(Smem& s,
    const float* __restrict__ A, const float* __restrict__ W,
    int kb, int kcnt, ull acc[4][4])
{
    const int tid = threadIdx.x;
    const int tx = tid & 31;
    const int ty4 = (tid >> 5) << 2;
    const int ar = tid >> 3;            // staging: A row 0..63
    const int ac = (tid & 7) << 2;      // staging: A k-offset 0,4,...,28

    for (int k0 = kb; k0 < kb + kcnt; k0 += KCH) {
        // stage A: 64 x 32 (1 float4 per thread)
        {
            const float* src = &A[ar * 1024 + k0 + ac];
            float4 v;
            if (CG) v = __ldcg((const float4*)src);
            else    v = __ldg ((const float4*)src);
            *(float4*)&s.As[ar][ac] = v;
        }
        // stage W transposed: 256 n x 32 k (16 per thread, coalesced)
        #pragma unroll
        for (int i = 0; i < 16; i++) {
            int e = tid + i * 512;
            int n = e >> 5, kk = e & 31;
            s.Ws[kk][n] = __ldg(&W[n * 1024 + k0 + kk]);
        }
        __syncthreads();
        #pragma unroll
        for (int k = 0; k < KCH; k++) {
            ull ad[4], w_[4];
            #pragma unroll
            for (int i = 0; i < 4; i++) ad[i] = dup2(s.As[ty4 + i][k]);
            #pragma unroll
            for (int m = 0; m < 4; m++)
                w_[m] = *(const ull*)&s.Ws[k][m * 64 + tx * 2];
            #pragma unroll
            for (int i = 0; i < 4; i++)
                #pragma unroll
                for (int m = 0; m < 4; m++)
                    fma2(acc[i][m], ad[i], w_[m]);
        }
        __syncthreads();
    }
}

__device__ __forceinline__ void store_tile(float* __restrict__ Cp, int ldC,
                                           int n0, ull acc[4][4])
{
    const int tid = threadIdx.x;
    const int tx = tid & 31;
    const int ty4 = (tid >> 5) << 2;
    #pragma unroll
    for (int i = 0; i < 4; i++) {
        int b = ty4 + i;
        #pragma unroll
        for (int m = 0; m < 4; m++)
            *(float2*)&Cp[(size_t)b * ldC + n0 + m * 64 + tx * 2] =
                *(float2*)&acc[i][m];
    }
}

// ---------------------------------------------------------------------------
// Precompute: g_xw = x @ w_ih^T + b_ih + b_hh.  grid (4 n-tiles, 512 m-tiles)
// ---------------------------------------------------------------------------
__global__ __launch_bounds__(512) void xw_kernel(
    const float* __restrict__ x, const float* __restrict__ w_ih,
    const float* __restrict__ b_ih, const float* __restrict__ b_hh)
{
    __shared__ Smem s;
    const int n0 = blockIdx.x * 256;
    const int m0 = blockIdx.y * 64;
    const int tid = threadIdx.x;
    const int tx = tid & 31;
    const int ty4 = (tid >> 5) << 2;
    ull acc[4][4] = {};
    gemm_tile<false>(s, x + (size_t)m0 * 1024, w_ih + (size_t)n0 * 1024,
                     0, 1024, acc);
    #pragma unroll
    for (int i = 0; i < 4; i++) {
        size_t m = m0 + ty4 + i;
        #pragma unroll
        for (int m4 = 0; m4 < 4; m4++) {
            int n = n0 + m4 * 64 + tx * 2;
            float2 v = *(float2*)&acc[i][m4];
            v.x += __ldg(&b_ih[n])     + __ldg(&b_hh[n]);
            v.y += __ldg(&b_ih[n + 1]) + __ldg(&b_hh[n + 1]);
            *(float2*)&g_xw[m * Hz + n] = v;
        }
    }
}

// ---------------------------------------------------------------------------
// Persistent recurrent kernel: 512 steps, 128 CTAs x 512 threads.
// ---------------------------------------------------------------------------
__global__ __launch_bounds__(512, 1) void rnn_persistent(
    const float* __restrict__ eps, const float* __restrict__ w_hh,
    const float* __restrict__ w_g, const float* __restrict__ b_g,
    float* __restrict__ o_seq, float* __restrict__ o_prob,
    float* __restrict__ o_mu, float* __restrict__ o_std)
{
    __shared__ Smem s;
    const int cta = blockIdx.x;
    const int tid = threadIdx.x;
    const float LPC = -0.5f * 1.8378770664093453f * (float)Hz;

    unsigned gen = *(volatile unsigned*)&g_epoch;

    // zero recurrent state: 65536 elems / 65536 threads
    g_h[cta * 512 + tid] = 0.0f;
    grid_sync(gen);

    for (int t = 0; t < Tz; t++) {
        // ---- P0: o_prob(t-1) + GEMM1 partial: g_p1 = h @ w_hh^T -----------
        if (t > 0 && cta < Bz && tid == 0)
            o_prob[cta * Tz + (t - 1)] =
                __ldcg(&g_lpp[cta][0]) + __ldcg(&g_lpp[cta][1]) + LPC;
        {
            const int n0 = (cta & 3) * 256;
            const int sl = cta >> 2;                 // 0..31, K=32
            ull acc[4][4] = {};
            gemm_tile<true>(s, g_h, w_hh + (size_t)n0 * 1024,
                            sl * 32, 32, acc);
            store_tile(g_p1 + (size_t)sl * (Bz * Hz), Hz, n0, acc);
        }
        grid_sync(gen);

        // ---- P1: combine 32 partials + xw + tanh -> g_hrnn ----------------
        {
            int idx = cta * 512 + tid;               // b*1024 + j
            int b = idx >> 10, j = idx & 1023;
            float v = __ldg(&g_xw[((size_t)b * Tz + t) * Hz + j]);
            float p[NS1];
            #pragma unroll
            for (int sl = 0; sl < NS1; sl++)
                p[sl] = __ldcg(&g_p1[(size_t)sl * (Bz * Hz) + idx]);
            #pragma unroll
            for (int sl = 0; sl < NS1; sl++) v += p[sl];
            g_hrnn[idx] = tanhf(v);
        }
        grid_sync(gen);

        // ---- P2: GEMM2 partial: g_p2 = h_rnn @ w_g^T ----------------------
        {
            const int n0 = (cta & 7) * 256;
            const int sl = cta >> 3;                 // 0..15, K=64
            ull acc[4][4] = {};
            gemm_tile<true>(s, g_hrnn, w_g + (size_t)n0 * 1024,
                            sl * 64, 64, acc);
            store_tile(g_p2 + (size_t)sl * (Bz * H2z), H2z, n0, acc);
        }
        grid_sync(gen);

        // ---- P3: epilogue, half batch-row per CTA (512 j's, 1/thread) -----
        {
            const int b = cta >> 1;
            const int j = (cta & 1) * 512 + tid;
            float ss = __ldg(&b_g[j]);
            float sm = __ldg(&b_g[Hz + j]);
            #pragma unroll
            for (int sl = 0; sl < NS2; sl++) {
                const float* p = g_p2 + (size_t)sl * (Bz * H2z) + (size_t)b * H2z;
                ss += __ldcg(&p[j]);
                sm += __ldcg(&p[Hz + j]);
            }
            float sd = (ss > 20.0f) ? ss : log1pf(expf(ss));
            float e = __ldg(&eps[((size_t)b * Tz + t) * Hz + j]);
            float sample = sm + sd * e;
            size_t o = ((size_t)b * Tz + t) * Hz + j;
            o_seq[o] = sample;
            o_mu[o]  = sm;
            o_std[o] = sd;
            g_h[b * Hz + j] = sample;

            float lp = -0.5f * e * e - logf(sd);
            #pragma unroll
            for (int off = 16; off > 0; off >>= 1)
                lp += __shfl_xor_sync(0xffffffffu, lp, off);
            __shared__ float red[16];
            if ((tid & 31) == 0) red[tid >> 5] = lp;
            __syncthreads();
            if (tid == 0) {
                float sum = 0.0f;
                #pragma unroll
                for (int w = 0; w < 16; w++) sum += red[w];
                g_lpp[b][cta & 1] = sum;
            }
        }
        grid_sync(gen);
    }

    // final o_prob (t = 511)
    if (cta < Bz && tid == 0)
        o_prob[cta * Tz + (Tz - 1)] =
            __ldcg(&g_lpp[cta][0]) + __ldcg(&g_lpp[cta][1]) + LPC;

    // persist epoch for next graph replay (flags never reset)
    if (cta == 0 && tid == 0) *(volatile unsigned*)&g_epoch = gen;
}

// ---------------------------------------------------------------------------
extern "C" void kernel_launch(void* const* d_in, const int* in_sizes, int n_in,
                              void* d_out, int out_size)
{
    const float* x    = (const float*)d_in[0];
    const float* eps  = (const float*)d_in[1];
    const float* w_ih = (const float*)d_in[2];
    const float* w_hh = (const float*)d_in[3];
    const float* b_ih = (const float*)d_in[4];
    const float* b_hh = (const float*)d_in[5];
    const float* w_g  = (const float*)d_in[6];
    const float* b_g  = (const float*)d_in[7];

    float* out = (float*)d_out;
    float* o_seq  = out;
    float* o_prob = out + (size_t)Bz * Tz * Hz;
    float* o_mu   = o_prob + (size_t)Bz * Tz;
    float* o_std  = o_mu + (size_t)Bz * Tz * Hz;

    xw_kernel<<<dim3(4, 512), 512>>>(x, w_ih, b_ih, b_hh);
    rnn_persistent<<<NCTA, 512>>>(eps, w_hh, w_g, b_g,
                                  o_seq, o_prob, o_mu, o_std);
}